// round 11
// baseline (speedup 1.0000x reference)
#include <cuda_runtime.h>

#define TPB 256

// d values (level 0)
__device__ __align__(16) float g_d[12000032];
// pyramid: A1 (tile sums) at [0, n1), A2->S2 at [n1, n1+n2)
__device__ __align__(16) float g_lvl[900032];
__device__ double g_thr_part[65536];
__device__ double g_win_part[65536];

__device__ __forceinline__ int sidx(int i) { return i + (i >> 4); }  // 17-stride pad

__device__ __forceinline__ float edge_len(float2 a, float2 b) {
    float dx = __fsub_rn(a.x, b.x);
    float dy = __fsub_rn(a.y, b.y);
    float s  = __fmaf_rn(dy, dy, __fmul_rn(dx, dx));
    return __fsqrt_rn(s);
}

__device__ __forceinline__ double block_reduce_double(double v, double* swarp) {
    int lane = threadIdx.x & 31, wid = threadIdx.x >> 5;
    #pragma unroll
    for (int o = 16; o > 0; o >>= 1) v += __shfl_down_sync(0xffffffffu, v, o);
    if (lane == 0) swarp[wid] = v;
    __syncthreads();
    double r = 0.0;
    if (wid == 0) {
        r = (lane < (blockDim.x >> 5)) ? swarp[lane] : 0.0;
        #pragma unroll
        for (int o = 4; o > 0; o >>= 1) r += __shfl_down_sync(0xffffffffu, r, o);
    }
    return r;  // valid in thread 0
}

// Kernel A: edges + threshold partial + A1 (48/block) + A2 (3/block).
__global__ void edges_kernel(const float2* __restrict__ pts,
                             const int* __restrict__ faces, int F, int M,
                             long off2, int n1, int n2) {
    __shared__ float sd[816];
    __shared__ float sA1[48];
    __shared__ int   sfaces[768];
    __shared__ double swarp[8];
    int tid = threadIdx.x;
    int B0 = blockIdx.x * TPB;
    long ibase = (long)B0 * 3;
    int totalInts = 3 * F;

    if (ibase + 768 <= totalInts) {
        if (tid < 192) {
            const int4* f4 = reinterpret_cast<const int4*>(faces + ibase);
            reinterpret_cast<int4*>(sfaces)[tid] = f4[tid];
        }
    } else {
        for (int i = tid; i < 768; i += TPB)
            if (ibase + i < totalInts) sfaces[i] = faces[ibase + i];
    }
    __syncthreads();

    int f = B0 + tid;
    float facc = 0.0f;
    if (f < F) {
        int lb = 3 * tid;
        int i0 = sfaces[lb], i1 = sfaces[lb + 1], i2 = sfaces[lb + 2];
        float2 p0 = __ldg(&pts[i0]), p1 = __ldg(&pts[i1]), p2 = __ldg(&pts[i2]);
        float d0 = edge_len(p2, p0);
        float d1 = edge_len(p0, p1);
        float d2 = edge_len(p1, p2);
        sd[sidx(lb)] = d0; sd[sidx(lb + 1)] = d1; sd[sidx(lb + 2)] = d2;
        if (d0 < 7.0f) { float s = __fsub_rn(7.0f, d0); facc += __fmul_rn(s, s); }
        if (d1 < 7.0f) { float s = __fsub_rn(7.0f, d1); facc += __fmul_rn(s, s); }
        if (d2 < 7.0f) { float s = __fsub_rn(7.0f, d2); facc += __fmul_rn(s, s); }
    }
    __syncthreads();

    int gbase = B0 * 3;
    int lim = M - gbase;
    #pragma unroll
    for (int k = 0; k < 3; k++) {
        int idx = tid + k * TPB;
        if (idx < lim) g_d[gbase + idx] = sd[sidx(idx)];
    }
    if (tid < 48) {
        float a = 0.0f;
        int lb = tid * 16;
        #pragma unroll
        for (int i = 0; i < 16; i++) {
            if (lb + i < lim) a = __fadd_rn(a, sd[sidx(lb + i)]);
        }
        sA1[tid] = a;
        int gt = blockIdx.x * 48 + tid;
        if (lb < lim && gt < n1) g_lvl[gt] = a;
    }
    __syncthreads();
    if (tid < 3) {
        int gt2 = blockIdx.x * 3 + tid;
        if (gt2 < n2) {
            int a1base = blockIdx.x * 48 + tid * 16;
            float a = 0.0f;
            #pragma unroll
            for (int i = 0; i < 16; i++) {
                if (a1base + i < n1) a = __fadd_rn(a, sA1[tid * 16 + i]);
            }
            if (a1base < n1) g_lvl[off2 + gt2] = a;
        }
    }
    double tot = block_reduce_double((double)facc, swarp);
    if (tid == 0) g_thr_part[blockIdx.x] = tot;
}

// Single-block: A2 -> A3 -> A4 -> A5 -> scan -> S4 -> S3 -> S2 (gmem in place).
__global__ void fused_mid(long off2, int n2) {
    __shared__ float sA3[3072];
    __shared__ float sA4[256];
    __shared__ float sA5[16];
    int tid = threadIdx.x, nt = blockDim.x;
    int n3 = (n2 + 15) / 16;
    int n4 = (n3 + 15) / 16;
    int n5 = (n4 + 15) / 16;
    for (int t = tid; t < n3; t += nt) {
        float a = 0.0f;
        int base = t * 16, l = n2 - base; if (l > 16) l = 16;
        #pragma unroll
        for (int i = 0; i < 16; i++) if (i < l) a = __fadd_rn(a, g_lvl[off2 + base + i]);
        sA3[t] = a;
    }
    __syncthreads();
    for (int t = tid; t < n4; t += nt) {
        float a = 0.0f;
        int base = t * 16, l = n3 - base; if (l > 16) l = 16;
        #pragma unroll
        for (int i = 0; i < 16; i++) if (i < l) a = __fadd_rn(a, sA3[base + i]);
        sA4[t] = a;
    }
    __syncthreads();
    for (int t = tid; t < n5; t += nt) {
        float a = 0.0f;
        int base = t * 16, l = n4 - base; if (l > 16) l = 16;
        #pragma unroll
        for (int i = 0; i < 16; i++) if (i < l) a = __fadd_rn(a, sA4[base + i]);
        sA5[t] = a;
    }
    __syncthreads();
    if (tid == 0) {
        float acc = 0.0f;
        for (int i = 0; i < n5; i++) { acc = __fadd_rn(acc, sA5[i]); sA5[i] = acc; }
    }
    __syncthreads();
    for (int t = tid; t < n5; t += nt) {
        float off = (t > 0) ? sA5[t - 1] : 0.0f;
        int base = t * 16, l = n4 - base; if (l > 16) l = 16;
        float acc = 0.0f;
        #pragma unroll
        for (int i = 0; i < 16; i++) if (i < l) {
            acc = __fadd_rn(acc, sA4[base + i]);
            sA4[base + i] = __fadd_rn(off, acc);
        }
    }
    __syncthreads();
    for (int t = tid; t < n4; t += nt) {
        float off = (t > 0) ? sA4[t - 1] : 0.0f;
        int base = t * 16, l = n3 - base; if (l > 16) l = 16;
        float acc = 0.0f;
        #pragma unroll
        for (int i = 0; i < 16; i++) if (i < l) {
            acc = __fadd_rn(acc, sA3[base + i]);
            sA3[base + i] = __fadd_rn(off, acc);
        }
    }
    __syncthreads();
    for (int t = tid; t < n3; t += nt) {
        float off = (t > 0) ? sA3[t - 1] : 0.0f;
        int base = t * 16, l = n2 - base; if (l > 16) l = 16;
        float acc = 0.0f;
        #pragma unroll
        for (int i = 0; i < 16; i++) if (i < l) {
            acc = __fadd_rn(acc, g_lvl[off2 + base + i]);
            g_lvl[off2 + base + i] = __fadd_rn(off, acc);
        }
    }
}

// S1[k] reconstructed on the fly (bitwise = up1).
__device__ __forceinline__ float s1_val(int k, long off2, int n1) {
    int p = k >> 4, r = k & 15;
    float off = (p > 0) ? g_lvl[off2 + p - 1] : 0.0f;
    float acc = 0.0f;
    int base = p * 16;
    #pragma unroll
    for (int i = 0; i < 16; i++) {
        if (i <= r && base + i < n1) acc = __fadd_rn(acc, g_lvl[base + i]);
    }
    return __fadd_rn(off, acc);
}

// Kernel B: reconstruct S0 per tile from d + (A1,S2), then windows.
__global__ void window_kernel(int M, int Mj, int nTiles, long off2) {
    __shared__ float s[4448];
    __shared__ double swarp[8];
    int tid = threadIdx.x;
    int T0 = blockIdx.x * TPB;
    int dstart = 16 * (T0 - 1);
    for (int idx = tid; idx < 258 * 16; idx += TPB) {
        int g = dstart + idx;
        float v = (g >= 0 && g < M) ? g_d[g] : 0.0f;
        s[sidx(idx)] = v;
    }
    __syncthreads();
    for (int lt = tid; lt < 258; lt += TPB) {
        int gt = T0 - 1 + lt;
        if (gt >= 0 && gt < nTiles) {
            float off = (gt > 0) ? s1_val(gt - 1, off2, nTiles) : 0.0f;
            float a = 0.0f;
            int lb = lt * 16;
            #pragma unroll
            for (int i = 0; i < 16; i++) {
                int p = sidx(lb + i);
                a = __fadd_rn(a, s[p]);
                s[p] = __fadd_rn(off, a);
            }
        }
    }
    __syncthreads();
    float facc = 0.0f;
    int gt = T0 + tid;
    if (gt < nTiles) {
        int lb = (tid + 1) * 16;
        bool full = (gt * 16 + 15 < Mj) && (gt > 0);
        if (full) {
            // Interior fast path: no per-element branches; j >= 16 so both divisors are 5.
            #pragma unroll
            for (int i = 0; i < 16; i++) {
                int lj = lb + i;
                float sj = s[sidx(lj)];
                float sn = s[sidx(lj + 5)];
                float lo = s[sidx(lj - 5)];
                float a = __fsub_rn(sj, lo);
                float b = __fsub_rn(sn, sj);
                float diff = fabsf(__fsub_rn(__fmul_rn(b, 0.2f), __fmul_rn(a, 0.2f)));
                facc += __expf(diff);
            }
        } else {
            #pragma unroll
            for (int i = 0; i < 16; i++) {
                int j = gt * 16 + i;
                if (j < Mj) {
                    int lj = lb + i;
                    float sj = s[sidx(lj)];
                    float sn = s[sidx(lj + 5)];
                    float lo = (j >= 5) ? s[sidx(lj - 5)] : 0.0f;
                    float a = __fsub_rn(sj, lo);
                    float b = __fsub_rn(sn, sj);
                    float avg_prev;
                    if (j >= 4) avg_prev = __fmul_rn(a, 0.2f);
                    else        avg_prev = __fdiv_rn(a, (float)(j + 1));
                    float avg_next = __fmul_rn(b, 0.2f);
                    float diff = fabsf(__fsub_rn(avg_next, avg_prev));
                    facc += __expf(diff);
                }
            }
        }
    }
    double tot = block_reduce_double((double)facc, swarp);
    if (tid == 0) g_win_part[blockIdx.x] = tot;
}

// Final: 1024 threads, 4 independent partial chains per thread (MLP>=4 hides L2 latency).
__global__ void final_kernel(int np_thr, int np_win, float* __restrict__ out) {
    __shared__ double swarp[32];
    int tid = threadIdx.x;
    int nt = blockDim.x;
    double a0 = 0.0, a1 = 0.0, a2 = 0.0, a3 = 0.0;
    for (int i = tid * 4; i < np_thr; i += nt * 4) {
        if (i     < np_thr) a0 += g_thr_part[i];
        if (i + 1 < np_thr) a1 += g_thr_part[i + 1];
        if (i + 2 < np_thr) a2 += g_thr_part[i + 2];
        if (i + 3 < np_thr) a3 += g_thr_part[i + 3];
    }
    for (int i = tid * 4; i < np_win; i += nt * 4) {
        if (i     < np_win) a0 += g_win_part[i];
        if (i + 1 < np_win) a1 += g_win_part[i + 1];
        if (i + 2 < np_win) a2 += g_win_part[i + 2];
        if (i + 3 < np_win) a3 += g_win_part[i + 3];
    }
    double v = (a0 + a1) + (a2 + a3);
    int lane = tid & 31, wid = tid >> 5;
    #pragma unroll
    for (int o = 16; o > 0; o >>= 1) v += __shfl_down_sync(0xffffffffu, v, o);
    if (lane == 0) swarp[wid] = v;
    __syncthreads();
    if (wid == 0) {
        double r = (lane < (nt >> 5)) ? swarp[lane] : 0.0;
        #pragma unroll
        for (int o = 16; o > 0; o >>= 1) r += __shfl_down_sync(0xffffffffu, r, o);
        if (tid == 0) out[0] = (float)r;
    }
}

extern "C" void kernel_launch(void* const* d_in, const int* in_sizes, int n_in,
                              void* d_out, int out_size) {
    const float2* pts = (const float2*)d_in[0];
    const int* faces = (const int*)d_in[1];
    int M = in_sizes[1];      // 3 * F
    int F = M / 3;

    int n1 = (M + 15) / 16;
    int n2 = (n1 + 15) / 16;
    long off2 = n1;

    int nb_f = (F + TPB - 1) / TPB;
    edges_kernel<<<nb_f, TPB>>>(pts, faces, F, M, off2, n1, n2);

    fused_mid<<<1, 1024>>>(off2, n2);

    int Mj = M - 5;
    int nb_w = (n1 + TPB - 1) / TPB;
    window_kernel<<<nb_w, TPB>>>(M, Mj, n1, off2);

    final_kernel<<<1, 1024>>>(nb_f, nb_w, (float*)d_out);
}

// round 12
// speedup vs baseline: 1.5644x; 1.5644x over previous
#include <cuda_runtime.h>

#define TPB 256

// d values (level 0)
__device__ __align__(16) float g_d[12000032];
// pyramid: A1 (tile sums) at [0, n1), A2->S2 at [n1, n1+n2)
__device__ __align__(16) float g_lvl[900032];
__device__ double g_thr_part[65536];
__device__ double g_win_part[65536];
__device__ double g_fin[32];

__device__ __forceinline__ int sidx(int i) { return i + (i >> 4); }  // 17-stride pad

__device__ __forceinline__ float edge_len(float2 a, float2 b) {
    float dx = __fsub_rn(a.x, b.x);
    float dy = __fsub_rn(a.y, b.y);
    float s  = __fmaf_rn(dy, dy, __fmul_rn(dx, dx));
    return __fsqrt_rn(s);
}

__device__ __forceinline__ double block_reduce_double(double v, double* swarp) {
    int lane = threadIdx.x & 31, wid = threadIdx.x >> 5;
    #pragma unroll
    for (int o = 16; o > 0; o >>= 1) v += __shfl_down_sync(0xffffffffu, v, o);
    if (lane == 0) swarp[wid] = v;
    __syncthreads();
    double r = 0.0;
    if (wid == 0) {
        r = (lane < (blockDim.x >> 5)) ? swarp[lane] : 0.0;
        #pragma unroll
        for (int o = 4; o > 0; o >>= 1) r += __shfl_down_sync(0xffffffffu, r, o);
    }
    return r;  // valid in thread 0
}

// Kernel A: edges + threshold partial + A1 (48/block) + A2 (3/block).
__global__ void edges_kernel(const float2* __restrict__ pts,
                             const int* __restrict__ faces, int F, int M,
                             long off2, int n1, int n2) {
    __shared__ float sd[816];
    __shared__ float sA1[48];
    __shared__ int   sfaces[768];
    __shared__ double swarp[8];
    int tid = threadIdx.x;
    int B0 = blockIdx.x * TPB;
    long ibase = (long)B0 * 3;
    int totalInts = 3 * F;

    if (ibase + 768 <= totalInts) {
        if (tid < 192) {
            const int4* f4 = reinterpret_cast<const int4*>(faces + ibase);
            reinterpret_cast<int4*>(sfaces)[tid] = f4[tid];
        }
    } else {
        for (int i = tid; i < 768; i += TPB)
            if (ibase + i < totalInts) sfaces[i] = faces[ibase + i];
    }
    __syncthreads();

    int f = B0 + tid;
    float facc = 0.0f;
    if (f < F) {
        int lb = 3 * tid;
        int i0 = sfaces[lb], i1 = sfaces[lb + 1], i2 = sfaces[lb + 2];
        float2 p0 = __ldg(&pts[i0]), p1 = __ldg(&pts[i1]), p2 = __ldg(&pts[i2]);
        float d0 = edge_len(p2, p0);
        float d1 = edge_len(p0, p1);
        float d2 = edge_len(p1, p2);
        sd[sidx(lb)] = d0; sd[sidx(lb + 1)] = d1; sd[sidx(lb + 2)] = d2;
        if (d0 < 7.0f) { float s = __fsub_rn(7.0f, d0); facc += __fmul_rn(s, s); }
        if (d1 < 7.0f) { float s = __fsub_rn(7.0f, d1); facc += __fmul_rn(s, s); }
        if (d2 < 7.0f) { float s = __fsub_rn(7.0f, d2); facc += __fmul_rn(s, s); }
    }
    __syncthreads();

    int gbase = B0 * 3;
    int lim = M - gbase;
    #pragma unroll
    for (int k = 0; k < 3; k++) {
        int idx = tid + k * TPB;
        if (idx < lim) g_d[gbase + idx] = sd[sidx(idx)];
    }
    if (tid < 48) {
        float a = 0.0f;
        int lb = tid * 16;
        #pragma unroll
        for (int i = 0; i < 16; i++) {
            if (lb + i < lim) a = __fadd_rn(a, sd[sidx(lb + i)]);
        }
        sA1[tid] = a;
        int gt = blockIdx.x * 48 + tid;
        if (lb < lim && gt < n1) g_lvl[gt] = a;
    }
    __syncthreads();
    if (tid < 3) {
        int gt2 = blockIdx.x * 3 + tid;
        if (gt2 < n2) {
            int a1base = blockIdx.x * 48 + tid * 16;
            float a = 0.0f;
            #pragma unroll
            for (int i = 0; i < 16; i++) {
                if (a1base + i < n1) a = __fadd_rn(a, sA1[tid * 16 + i]);
            }
            if (a1base < n1) g_lvl[off2 + gt2] = a;
        }
    }
    double tot = block_reduce_double((double)facc, swarp);
    if (tid == 0) g_thr_part[blockIdx.x] = tot;
}

// Single-block: A2 -> A3 -> A4 -> A5 -> scan -> S4 -> S3 -> S2 (gmem in place).
__global__ void fused_mid(long off2, int n2) {
    __shared__ float sA3[3072];
    __shared__ float sA4[256];
    __shared__ float sA5[16];
    int tid = threadIdx.x, nt = blockDim.x;
    int n3 = (n2 + 15) / 16;
    int n4 = (n3 + 15) / 16;
    int n5 = (n4 + 15) / 16;
    for (int t = tid; t < n3; t += nt) {
        float a = 0.0f;
        int base = t * 16, l = n2 - base; if (l > 16) l = 16;
        #pragma unroll
        for (int i = 0; i < 16; i++) if (i < l) a = __fadd_rn(a, g_lvl[off2 + base + i]);
        sA3[t] = a;
    }
    __syncthreads();
    for (int t = tid; t < n4; t += nt) {
        float a = 0.0f;
        int base = t * 16, l = n3 - base; if (l > 16) l = 16;
        #pragma unroll
        for (int i = 0; i < 16; i++) if (i < l) a = __fadd_rn(a, sA3[base + i]);
        sA4[t] = a;
    }
    __syncthreads();
    for (int t = tid; t < n5; t += nt) {
        float a = 0.0f;
        int base = t * 16, l = n4 - base; if (l > 16) l = 16;
        #pragma unroll
        for (int i = 0; i < 16; i++) if (i < l) a = __fadd_rn(a, sA4[base + i]);
        sA5[t] = a;
    }
    __syncthreads();
    if (tid == 0) {
        float acc = 0.0f;
        for (int i = 0; i < n5; i++) { acc = __fadd_rn(acc, sA5[i]); sA5[i] = acc; }
    }
    __syncthreads();
    for (int t = tid; t < n5; t += nt) {
        float off = (t > 0) ? sA5[t - 1] : 0.0f;
        int base = t * 16, l = n4 - base; if (l > 16) l = 16;
        float acc = 0.0f;
        #pragma unroll
        for (int i = 0; i < 16; i++) if (i < l) {
            acc = __fadd_rn(acc, sA4[base + i]);
            sA4[base + i] = __fadd_rn(off, acc);
        }
    }
    __syncthreads();
    for (int t = tid; t < n4; t += nt) {
        float off = (t > 0) ? sA4[t - 1] : 0.0f;
        int base = t * 16, l = n3 - base; if (l > 16) l = 16;
        float acc = 0.0f;
        #pragma unroll
        for (int i = 0; i < 16; i++) if (i < l) {
            acc = __fadd_rn(acc, sA3[base + i]);
            sA3[base + i] = __fadd_rn(off, acc);
        }
    }
    __syncthreads();
    for (int t = tid; t < n3; t += nt) {
        float off = (t > 0) ? sA3[t - 1] : 0.0f;
        int base = t * 16, l = n2 - base; if (l > 16) l = 16;
        float acc = 0.0f;
        #pragma unroll
        for (int i = 0; i < 16; i++) if (i < l) {
            acc = __fadd_rn(acc, g_lvl[off2 + base + i]);
            g_lvl[off2 + base + i] = __fadd_rn(off, acc);
        }
    }
}

// S1[k] reconstructed on the fly (bitwise = up1).
__device__ __forceinline__ float s1_val(int k, long off2, int n1) {
    int p = k >> 4, r = k & 15;
    float off = (p > 0) ? g_lvl[off2 + p - 1] : 0.0f;
    float acc = 0.0f;
    int base = p * 16;
    #pragma unroll
    for (int i = 0; i < 16; i++) {
        if (i <= r && base + i < n1) acc = __fadd_rn(acc, g_lvl[base + i]);
    }
    return __fadd_rn(off, acc);
}

// Kernel B: reconstruct S0 per tile from d + (A1,S2), then windows. (R6 body, measured good.)
__global__ void window_kernel(int M, int Mj, int nTiles, long off2) {
    __shared__ float s[4448];
    __shared__ double swarp[8];
    int tid = threadIdx.x;
    int T0 = blockIdx.x * TPB;
    int dstart = 16 * (T0 - 1);
    for (int idx = tid; idx < 258 * 16; idx += TPB) {
        int g = dstart + idx;
        float v = (g >= 0 && g < M) ? g_d[g] : 0.0f;
        s[sidx(idx)] = v;
    }
    __syncthreads();
    for (int lt = tid; lt < 258; lt += TPB) {
        int gt = T0 - 1 + lt;
        if (gt >= 0 && gt < nTiles) {
            float off = (gt > 0) ? s1_val(gt - 1, off2, nTiles) : 0.0f;
            float a = 0.0f;
            int lb = lt * 16;
            #pragma unroll
            for (int i = 0; i < 16; i++) {
                int p = sidx(lb + i);
                a = __fadd_rn(a, s[p]);
                s[p] = __fadd_rn(off, a);
            }
        }
    }
    __syncthreads();
    float facc = 0.0f;
    int gt = T0 + tid;
    if (gt < nTiles) {
        int lb = (tid + 1) * 16;
        #pragma unroll
        for (int i = 0; i < 16; i++) {
            int j = gt * 16 + i;
            if (j < Mj) {
                int lj = lb + i;
                float sj = s[sidx(lj)];
                float sn = s[sidx(lj + 5)];
                float lo = (j >= 5) ? s[sidx(lj - 5)] : 0.0f;
                float a = __fsub_rn(sj, lo);
                float b = __fsub_rn(sn, sj);
                float avg_prev;
                if (j >= 4) avg_prev = __fmul_rn(a, 0.2f);
                else        avg_prev = __fdiv_rn(a, (float)(j + 1));
                float avg_next = __fmul_rn(b, 0.2f);
                float diff = fabsf(__fsub_rn(avg_next, avg_prev));
                facc += __expf(diff);
            }
        }
    }
    double tot = block_reduce_double((double)facc, swarp);
    if (tid == 0) g_win_part[blockIdx.x] = tot;
}

// Final stage 1: 32 blocks spread across SMs; deterministic fixed-tree reduction.
__global__ void final1_kernel(int np_thr, int np_win) {
    __shared__ double swarp[8];
    int tid = threadIdx.x;
    int gid = blockIdx.x * TPB + tid;
    int stride = gridDim.x * TPB;
    int total = np_thr + np_win;
    double v = 0.0;
    for (int i = gid; i < total; i += stride)
        v += (i < np_thr) ? g_thr_part[i] : g_win_part[i - np_thr];
    double tot = block_reduce_double(v, swarp);
    if (tid == 0) g_fin[blockIdx.x] = tot;
}

// Final stage 2: one warp.
__global__ void final2_kernel(int nb, float* __restrict__ out) {
    int lane = threadIdx.x;
    double v = (lane < nb) ? g_fin[lane] : 0.0;
    #pragma unroll
    for (int o = 16; o > 0; o >>= 1) v += __shfl_down_sync(0xffffffffu, v, o);
    if (lane == 0) out[0] = (float)v;
}

extern "C" void kernel_launch(void* const* d_in, const int* in_sizes, int n_in,
                              void* d_out, int out_size) {
    const float2* pts = (const float2*)d_in[0];
    const int* faces = (const int*)d_in[1];
    int M = in_sizes[1];      // 3 * F
    int F = M / 3;

    int n1 = (M + 15) / 16;
    int n2 = (n1 + 15) / 16;
    long off2 = n1;

    int nb_f = (F + TPB - 1) / TPB;
    edges_kernel<<<nb_f, TPB>>>(pts, faces, F, M, off2, n1, n2);

    fused_mid<<<1, 1024>>>(off2, n2);

    int Mj = M - 5;
    int nb_w = (n1 + TPB - 1) / TPB;
    window_kernel<<<nb_w, TPB>>>(M, Mj, n1, off2);

    final1_kernel<<<32, TPB>>>(nb_f, nb_w);
    final2_kernel<<<1, 32>>>(32, (float*)d_out);
}

// round 13
// speedup vs baseline: 1.5769x; 1.0080x over previous
#include <cuda_runtime.h>

#define TPB 256

// d values (level 0)
__device__ __align__(16) float g_d[12000032];
// pyramid: A1 (tile sums) at [0, n1), A2->S2 at [n1, n1+n2)
__device__ __align__(16) float g_lvl[900032];
__device__ double g_thr_part[65536];
__device__ double g_win_part[65536];
__device__ double g_fin[256];

__device__ __forceinline__ int sidx(int i) { return i + (i >> 4); }  // 17-stride pad

__device__ __forceinline__ float edge_len(float2 a, float2 b) {
    float dx = __fsub_rn(a.x, b.x);
    float dy = __fsub_rn(a.y, b.y);
    float s  = __fmaf_rn(dy, dy, __fmul_rn(dx, dx));
    return __fsqrt_rn(s);
}

__device__ __forceinline__ double block_reduce_double(double v, double* swarp) {
    int lane = threadIdx.x & 31, wid = threadIdx.x >> 5;
    #pragma unroll
    for (int o = 16; o > 0; o >>= 1) v += __shfl_down_sync(0xffffffffu, v, o);
    if (lane == 0) swarp[wid] = v;
    __syncthreads();
    double r = 0.0;
    if (wid == 0) {
        r = (lane < (blockDim.x >> 5)) ? swarp[lane] : 0.0;
        #pragma unroll
        for (int o = 4; o > 0; o >>= 1) r += __shfl_down_sync(0xffffffffu, r, o);
    }
    return r;  // valid in thread 0
}

// Kernel A: edges + threshold partial + A1 (48/block) + A2 (3/block).
__global__ void edges_kernel(const float2* __restrict__ pts,
                             const int* __restrict__ faces, int F, int M,
                             long off2, int n1, int n2) {
    __shared__ float sd[816];
    __shared__ float sA1[48];
    __shared__ int   sfaces[768];
    __shared__ double swarp[8];
    int tid = threadIdx.x;
    int B0 = blockIdx.x * TPB;
    long ibase = (long)B0 * 3;
    int totalInts = 3 * F;

    if (ibase + 768 <= totalInts) {
        if (tid < 192) {
            const int4* f4 = reinterpret_cast<const int4*>(faces + ibase);
            reinterpret_cast<int4*>(sfaces)[tid] = f4[tid];
        }
    } else {
        for (int i = tid; i < 768; i += TPB)
            if (ibase + i < totalInts) sfaces[i] = faces[ibase + i];
    }
    __syncthreads();

    int f = B0 + tid;
    float facc = 0.0f;
    if (f < F) {
        int lb = 3 * tid;
        int i0 = sfaces[lb], i1 = sfaces[lb + 1], i2 = sfaces[lb + 2];
        float2 p0 = __ldg(&pts[i0]), p1 = __ldg(&pts[i1]), p2 = __ldg(&pts[i2]);
        float d0 = edge_len(p2, p0);
        float d1 = edge_len(p0, p1);
        float d2 = edge_len(p1, p2);
        sd[sidx(lb)] = d0; sd[sidx(lb + 1)] = d1; sd[sidx(lb + 2)] = d2;
        if (d0 < 7.0f) { float s = __fsub_rn(7.0f, d0); facc += __fmul_rn(s, s); }
        if (d1 < 7.0f) { float s = __fsub_rn(7.0f, d1); facc += __fmul_rn(s, s); }
        if (d2 < 7.0f) { float s = __fsub_rn(7.0f, d2); facc += __fmul_rn(s, s); }
    }
    __syncthreads();

    int gbase = B0 * 3;
    int lim = M - gbase;
    #pragma unroll
    for (int k = 0; k < 3; k++) {
        int idx = tid + k * TPB;
        if (idx < lim) g_d[gbase + idx] = sd[sidx(idx)];
    }
    if (tid < 48) {
        float a = 0.0f;
        int lb = tid * 16;
        #pragma unroll
        for (int i = 0; i < 16; i++) {
            if (lb + i < lim) a = __fadd_rn(a, sd[sidx(lb + i)]);
        }
        sA1[tid] = a;
        int gt = blockIdx.x * 48 + tid;
        if (lb < lim && gt < n1) g_lvl[gt] = a;
    }
    __syncthreads();
    if (tid < 3) {
        int gt2 = blockIdx.x * 3 + tid;
        if (gt2 < n2) {
            int a1base = blockIdx.x * 48 + tid * 16;
            float a = 0.0f;
            #pragma unroll
            for (int i = 0; i < 16; i++) {
                if (a1base + i < n1) a = __fadd_rn(a, sA1[tid * 16 + i]);
            }
            if (a1base < n1) g_lvl[off2 + gt2] = a;
        }
    }
    double tot = block_reduce_double((double)facc, swarp);
    if (tid == 0) g_thr_part[blockIdx.x] = tot;
}

// Single-block: A2 -> A3 -> A4 -> A5 -> scan -> S4 -> S3 -> S2 (gmem in place).
__global__ void fused_mid(long off2, int n2) {
    __shared__ float sA3[3072];
    __shared__ float sA4[256];
    __shared__ float sA5[16];
    int tid = threadIdx.x, nt = blockDim.x;
    int n3 = (n2 + 15) / 16;
    int n4 = (n3 + 15) / 16;
    int n5 = (n4 + 15) / 16;
    for (int t = tid; t < n3; t += nt) {
        float a = 0.0f;
        int base = t * 16, l = n2 - base; if (l > 16) l = 16;
        #pragma unroll
        for (int i = 0; i < 16; i++) if (i < l) a = __fadd_rn(a, g_lvl[off2 + base + i]);
        sA3[t] = a;
    }
    __syncthreads();
    for (int t = tid; t < n4; t += nt) {
        float a = 0.0f;
        int base = t * 16, l = n3 - base; if (l > 16) l = 16;
        #pragma unroll
        for (int i = 0; i < 16; i++) if (i < l) a = __fadd_rn(a, sA3[base + i]);
        sA4[t] = a;
    }
    __syncthreads();
    for (int t = tid; t < n5; t += nt) {
        float a = 0.0f;
        int base = t * 16, l = n4 - base; if (l > 16) l = 16;
        #pragma unroll
        for (int i = 0; i < 16; i++) if (i < l) a = __fadd_rn(a, sA4[base + i]);
        sA5[t] = a;
    }
    __syncthreads();
    if (tid == 0) {
        float acc = 0.0f;
        for (int i = 0; i < n5; i++) { acc = __fadd_rn(acc, sA5[i]); sA5[i] = acc; }
    }
    __syncthreads();
    for (int t = tid; t < n5; t += nt) {
        float off = (t > 0) ? sA5[t - 1] : 0.0f;
        int base = t * 16, l = n4 - base; if (l > 16) l = 16;
        float acc = 0.0f;
        #pragma unroll
        for (int i = 0; i < 16; i++) if (i < l) {
            acc = __fadd_rn(acc, sA4[base + i]);
            sA4[base + i] = __fadd_rn(off, acc);
        }
    }
    __syncthreads();
    for (int t = tid; t < n4; t += nt) {
        float off = (t > 0) ? sA4[t - 1] : 0.0f;
        int base = t * 16, l = n3 - base; if (l > 16) l = 16;
        float acc = 0.0f;
        #pragma unroll
        for (int i = 0; i < 16; i++) if (i < l) {
            acc = __fadd_rn(acc, sA3[base + i]);
            sA3[base + i] = __fadd_rn(off, acc);
        }
    }
    __syncthreads();
    for (int t = tid; t < n3; t += nt) {
        float off = (t > 0) ? sA3[t - 1] : 0.0f;
        int base = t * 16, l = n2 - base; if (l > 16) l = 16;
        float acc = 0.0f;
        #pragma unroll
        for (int i = 0; i < 16; i++) if (i < l) {
            acc = __fadd_rn(acc, g_lvl[off2 + base + i]);
            g_lvl[off2 + base + i] = __fadd_rn(off, acc);
        }
    }
}

// S1[k] reconstructed on the fly (bitwise = up1).
__device__ __forceinline__ float s1_val(int k, long off2, int n1) {
    int p = k >> 4, r = k & 15;
    float off = (p > 0) ? g_lvl[off2 + p - 1] : 0.0f;
    float acc = 0.0f;
    int base = p * 16;
    #pragma unroll
    for (int i = 0; i < 16; i++) {
        if (i <= r && base + i < n1) acc = __fadd_rn(acc, g_lvl[base + i]);
    }
    return __fadd_rn(off, acc);
}

// Kernel B: reconstruct S0 per tile from d + (A1,S2), then windows. (measured-good body)
__global__ void window_kernel(int M, int Mj, int nTiles, long off2) {
    __shared__ float s[4448];
    __shared__ double swarp[8];
    int tid = threadIdx.x;
    int T0 = blockIdx.x * TPB;
    int dstart = 16 * (T0 - 1);
    for (int idx = tid; idx < 258 * 16; idx += TPB) {
        int g = dstart + idx;
        float v = (g >= 0 && g < M) ? g_d[g] : 0.0f;
        s[sidx(idx)] = v;
    }
    __syncthreads();
    for (int lt = tid; lt < 258; lt += TPB) {
        int gt = T0 - 1 + lt;
        if (gt >= 0 && gt < nTiles) {
            float off = (gt > 0) ? s1_val(gt - 1, off2, nTiles) : 0.0f;
            float a = 0.0f;
            int lb = lt * 16;
            #pragma unroll
            for (int i = 0; i < 16; i++) {
                int p = sidx(lb + i);
                a = __fadd_rn(a, s[p]);
                s[p] = __fadd_rn(off, a);
            }
        }
    }
    __syncthreads();
    float facc = 0.0f;
    int gt = T0 + tid;
    if (gt < nTiles) {
        int lb = (tid + 1) * 16;
        #pragma unroll
        for (int i = 0; i < 16; i++) {
            int j = gt * 16 + i;
            if (j < Mj) {
                int lj = lb + i;
                float sj = s[sidx(lj)];
                float sn = s[sidx(lj + 5)];
                float lo = (j >= 5) ? s[sidx(lj - 5)] : 0.0f;
                float a = __fsub_rn(sj, lo);
                float b = __fsub_rn(sn, sj);
                float avg_prev;
                if (j >= 4) avg_prev = __fmul_rn(a, 0.2f);
                else        avg_prev = __fdiv_rn(a, (float)(j + 1));
                float avg_next = __fmul_rn(b, 0.2f);
                float diff = fabsf(__fsub_rn(avg_next, avg_prev));
                facc += __expf(diff);
            }
        }
    }
    double tot = block_reduce_double((double)facc, swarp);
    if (tid == 0) g_win_part[blockIdx.x] = tot;
}

// Final stage 1: 148 blocks (one wave, ~1KB each); deterministic fixed-tree reduction.
__global__ void final1_kernel(int np_thr, int np_win) {
    __shared__ double swarp[8];
    int tid = threadIdx.x;
    int gid = blockIdx.x * TPB + tid;
    int stride = gridDim.x * TPB;
    int total = np_thr + np_win;
    double v = 0.0;
    for (int i = gid; i < total; i += stride)
        v += (i < np_thr) ? g_thr_part[i] : g_win_part[i - np_thr];
    double tot = block_reduce_double(v, swarp);
    if (tid == 0) g_fin[blockIdx.x] = tot;
}

// Final stage 2: one block, covers up to 256 partials.
__global__ void final2_kernel(int nb, float* __restrict__ out) {
    __shared__ double swarp[8];
    int tid = threadIdx.x;
    double v = (tid < nb) ? g_fin[tid] : 0.0;
    double tot = block_reduce_double(v, swarp);
    if (tid == 0) out[0] = (float)tot;
}

extern "C" void kernel_launch(void* const* d_in, const int* in_sizes, int n_in,
                              void* d_out, int out_size) {
    const float2* pts = (const float2*)d_in[0];
    const int* faces = (const int*)d_in[1];
    int M = in_sizes[1];      // 3 * F
    int F = M / 3;

    int n1 = (M + 15) / 16;
    int n2 = (n1 + 15) / 16;
    long off2 = n1;

    int nb_f = (F + TPB - 1) / TPB;
    edges_kernel<<<nb_f, TPB>>>(pts, faces, F, M, off2, n1, n2);

    fused_mid<<<1, 1024>>>(off2, n2);

    int Mj = M - 5;
    int nb_w = (n1 + TPB - 1) / TPB;
    window_kernel<<<nb_w, TPB>>>(M, Mj, n1, off2);

    final1_kernel<<<148, TPB>>>(nb_f, nb_w);
    final2_kernel<<<1, 256>>>(148, (float*)d_out);
}

// round 15
// speedup vs baseline: 1.5800x; 1.0020x over previous
#include <cuda_runtime.h>

#define TPB 256

// d values (level 0)
__device__ __align__(16) float g_d[12000032];
// pyramid: A1 (tile sums) at [0, n1), A2->S2 at [n1, n1+n2)
__device__ __align__(16) float g_lvl[900032];
__device__ double g_thr_part[65536];
__device__ double g_win_part[65536];
__device__ double g_fin[256];

__device__ __forceinline__ int sidx(int i) { return i + (i >> 4); }  // 17-stride pad

__device__ __forceinline__ float edge_len(float2 a, float2 b) {
    float dx = __fsub_rn(a.x, b.x);
    float dy = __fsub_rn(a.y, b.y);
    float s  = __fmaf_rn(dy, dy, __fmul_rn(dx, dx));
    return __fsqrt_rn(s);
}

__device__ __forceinline__ double block_reduce_double(double v, double* swarp) {
    int lane = threadIdx.x & 31, wid = threadIdx.x >> 5;
    #pragma unroll
    for (int o = 16; o > 0; o >>= 1) v += __shfl_down_sync(0xffffffffu, v, o);
    if (lane == 0) swarp[wid] = v;
    __syncthreads();
    double r = 0.0;
    if (wid == 0) {
        r = (lane < (blockDim.x >> 5)) ? swarp[lane] : 0.0;
        #pragma unroll
        for (int o = 4; o > 0; o >>= 1) r += __shfl_down_sync(0xffffffffu, r, o);
    }
    return r;  // valid in thread 0
}

// Kernel A: edges + threshold partial + A1 (48/block) + A2 (3/block).
__global__ void edges_kernel(const float2* __restrict__ pts,
                             const int* __restrict__ faces, int F, int M,
                             long off2, int n1, int n2) {
    __shared__ float sd[816];
    __shared__ float sA1[48];
    __shared__ int   sfaces[768];
    __shared__ double swarp[8];
    int tid = threadIdx.x;
    int B0 = blockIdx.x * TPB;
    long ibase = (long)B0 * 3;
    int totalInts = 3 * F;

    if (ibase + 768 <= totalInts) {
        if (tid < 192) {
            const int4* f4 = reinterpret_cast<const int4*>(faces + ibase);
            reinterpret_cast<int4*>(sfaces)[tid] = f4[tid];
        }
    } else {
        for (int i = tid; i < 768; i += TPB)
            if (ibase + i < totalInts) sfaces[i] = faces[ibase + i];
    }
    __syncthreads();

    int f = B0 + tid;
    float facc = 0.0f;
    if (f < F) {
        int lb = 3 * tid;
        int i0 = sfaces[lb], i1 = sfaces[lb + 1], i2 = sfaces[lb + 2];
        float2 p0 = __ldg(&pts[i0]), p1 = __ldg(&pts[i1]), p2 = __ldg(&pts[i2]);
        float d0 = edge_len(p2, p0);
        float d1 = edge_len(p0, p1);
        float d2 = edge_len(p1, p2);
        sd[sidx(lb)] = d0; sd[sidx(lb + 1)] = d1; sd[sidx(lb + 2)] = d2;
        if (d0 < 7.0f) { float s = __fsub_rn(7.0f, d0); facc += __fmul_rn(s, s); }
        if (d1 < 7.0f) { float s = __fsub_rn(7.0f, d1); facc += __fmul_rn(s, s); }
        if (d2 < 7.0f) { float s = __fsub_rn(7.0f, d2); facc += __fmul_rn(s, s); }
    }
    __syncthreads();

    int gbase = B0 * 3;
    int lim = M - gbase;
    #pragma unroll
    for (int k = 0; k < 3; k++) {
        int idx = tid + k * TPB;
        if (idx < lim) g_d[gbase + idx] = sd[sidx(idx)];
    }
    if (tid < 48) {
        float a = 0.0f;
        int lb = tid * 16;
        #pragma unroll
        for (int i = 0; i < 16; i++) {
            if (lb + i < lim) a = __fadd_rn(a, sd[sidx(lb + i)]);
        }
        sA1[tid] = a;
        int gt = blockIdx.x * 48 + tid;
        if (lb < lim && gt < n1) g_lvl[gt] = a;
    }
    __syncthreads();
    if (tid < 3) {
        int gt2 = blockIdx.x * 3 + tid;
        if (gt2 < n2) {
            int a1base = blockIdx.x * 48 + tid * 16;
            float a = 0.0f;
            #pragma unroll
            for (int i = 0; i < 16; i++) {
                if (a1base + i < n1) a = __fadd_rn(a, sA1[tid * 16 + i]);
            }
            if (a1base < n1) g_lvl[off2 + gt2] = a;
        }
    }
    double tot = block_reduce_double((double)facc, swarp);
    if (tid == 0) g_thr_part[blockIdx.x] = tot;
}

// Single-block: A2 -> A3 -> A4 -> A5 -> scan -> S4 -> S3 -> S2 (gmem in place).
__global__ void fused_mid(long off2, int n2) {
    __shared__ float sA3[3072];
    __shared__ float sA4[256];
    __shared__ float sA5[16];
    int tid = threadIdx.x, nt = blockDim.x;
    int n3 = (n2 + 15) / 16;
    int n4 = (n3 + 15) / 16;
    int n5 = (n4 + 15) / 16;
    for (int t = tid; t < n3; t += nt) {
        float a = 0.0f;
        int base = t * 16, l = n2 - base; if (l > 16) l = 16;
        #pragma unroll
        for (int i = 0; i < 16; i++) if (i < l) a = __fadd_rn(a, g_lvl[off2 + base + i]);
        sA3[t] = a;
    }
    __syncthreads();
    for (int t = tid; t < n4; t += nt) {
        float a = 0.0f;
        int base = t * 16, l = n3 - base; if (l > 16) l = 16;
        #pragma unroll
        for (int i = 0; i < 16; i++) if (i < l) a = __fadd_rn(a, sA3[base + i]);
        sA4[t] = a;
    }
    __syncthreads();
    for (int t = tid; t < n5; t += nt) {
        float a = 0.0f;
        int base = t * 16, l = n4 - base; if (l > 16) l = 16;
        #pragma unroll
        for (int i = 0; i < 16; i++) if (i < l) a = __fadd_rn(a, sA4[base + i]);
        sA5[t] = a;
    }
    __syncthreads();
    if (tid == 0) {
        float acc = 0.0f;
        for (int i = 0; i < n5; i++) { acc = __fadd_rn(acc, sA5[i]); sA5[i] = acc; }
    }
    __syncthreads();
    for (int t = tid; t < n5; t += nt) {
        float off = (t > 0) ? sA5[t - 1] : 0.0f;
        int base = t * 16, l = n4 - base; if (l > 16) l = 16;
        float acc = 0.0f;
        #pragma unroll
        for (int i = 0; i < 16; i++) if (i < l) {
            acc = __fadd_rn(acc, sA4[base + i]);
            sA4[base + i] = __fadd_rn(off, acc);
        }
    }
    __syncthreads();
    for (int t = tid; t < n4; t += nt) {
        float off = (t > 0) ? sA4[t - 1] : 0.0f;
        int base = t * 16, l = n3 - base; if (l > 16) l = 16;
        float acc = 0.0f;
        #pragma unroll
        for (int i = 0; i < 16; i++) if (i < l) {
            acc = __fadd_rn(acc, sA3[base + i]);
            sA3[base + i] = __fadd_rn(off, acc);
        }
    }
    __syncthreads();
    for (int t = tid; t < n3; t += nt) {
        float off = (t > 0) ? sA3[t - 1] : 0.0f;
        int base = t * 16, l = n2 - base; if (l > 16) l = 16;
        float acc = 0.0f;
        #pragma unroll
        for (int i = 0; i < 16; i++) if (i < l) {
            acc = __fadd_rn(acc, g_lvl[off2 + base + i]);
            g_lvl[off2 + base + i] = __fadd_rn(off, acc);
        }
    }
}

// Kernel B: reconstruct S0 per tile from d + (A1,S2), then windows.
// S1 values needed by this block (range ~18 A1-groups) are precomputed once
// into smem with the exact same RN add sequence as s1_val/up1.
__global__ void window_kernel(int M, int Mj, int nTiles, long off2) {
    __shared__ float s[4448];
    __shared__ float sS1[288];     // 18 groups x 16 S1 values
    __shared__ double swarp[8];
    int tid = threadIdx.x;
    int T0 = blockIdx.x * TPB;
    int dstart = 16 * (T0 - 1);
    for (int idx = tid; idx < 258 * 16; idx += TPB) {
        int g = dstart + idx;
        float v = (g >= 0 && g < M) ? g_d[g] : 0.0f;
        s[sidx(idx)] = v;
    }
    // Precompute S1 for groups covering k in [T0-17, T0+255].
    int pbase = (T0 - 2) >> 4; if (pbase < 0) pbase = 0;
    if (tid < 18) {
        int p = pbase + tid;
        int base = p * 16;
        if (base < nTiles) {
            float off = (p > 0) ? g_lvl[off2 + p - 1] : 0.0f;
            float acc = 0.0f;
            #pragma unroll
            for (int i = 0; i < 16; i++) {
                int k = base + i;
                if (k < nTiles) {
                    acc = __fadd_rn(acc, g_lvl[k]);
                    sS1[tid * 16 + i] = __fadd_rn(off, acc);
                }
            }
        }
    }
    __syncthreads();
    int kbase = pbase * 16;
    for (int lt = tid; lt < 258; lt += TPB) {
        int gt = T0 - 1 + lt;
        if (gt >= 0 && gt < nTiles) {
            float off = (gt > 0) ? sS1[gt - 1 - kbase] : 0.0f;
            float a = 0.0f;
            int lb = lt * 16;
            #pragma unroll
            for (int i = 0; i < 16; i++) {
                int p = sidx(lb + i);
                a = __fadd_rn(a, s[p]);
                s[p] = __fadd_rn(off, a);
            }
        }
    }
    __syncthreads();
    float facc = 0.0f;
    int gt = T0 + tid;
    if (gt < nTiles) {
        int lb = (tid + 1) * 16;
        #pragma unroll
        for (int i = 0; i < 16; i++) {
            int j = gt * 16 + i;
            if (j < Mj) {
                int lj = lb + i;
                float sj = s[sidx(lj)];
                float sn = s[sidx(lj + 5)];
                float lo = (j >= 5) ? s[sidx(lj - 5)] : 0.0f;
                float a = __fsub_rn(sj, lo);
                float b = __fsub_rn(sn, sj);
                float avg_prev;
                if (j >= 4) avg_prev = __fmul_rn(a, 0.2f);
                else        avg_prev = __fdiv_rn(a, (float)(j + 1));
                float avg_next = __fmul_rn(b, 0.2f);
                float diff = fabsf(__fsub_rn(avg_next, avg_prev));
                facc += __expf(diff);
            }
        }
    }
    double tot = block_reduce_double((double)facc, swarp);
    if (tid == 0) g_win_part[blockIdx.x] = tot;
}

// Final stage 1: 148 blocks; deterministic fixed-tree reduction.
__global__ void final1_kernel(int np_thr, int np_win) {
    __shared__ double swarp[8];
    int tid = threadIdx.x;
    int gid = blockIdx.x * TPB + tid;
    int stride = gridDim.x * TPB;
    int total = np_thr + np_win;
    double v = 0.0;
    for (int i = gid; i < total; i += stride)
        v += (i < np_thr) ? g_thr_part[i] : g_win_part[i - np_thr];
    double tot = block_reduce_double(v, swarp);
    if (tid == 0) g_fin[blockIdx.x] = tot;
}

// Final stage 2: one block.
__global__ void final2_kernel(int nb, float* __restrict__ out) {
    __shared__ double swarp[8];
    int tid = threadIdx.x;
    double v = (tid < nb) ? g_fin[tid] : 0.0;
    double tot = block_reduce_double(v, swarp);
    if (tid == 0) out[0] = (float)tot;
}

extern "C" void kernel_launch(void* const* d_in, const int* in_sizes, int n_in,
                              void* d_out, int out_size) {
    const float2* pts = (const float2*)d_in[0];
    const int* faces = (const int*)d_in[1];
    int M = in_sizes[1];      // 3 * F
    int F = M / 3;

    int n1 = (M + 15) / 16;
    int n2 = (n1 + 15) / 16;
    long off2 = n1;

    int nb_f = (F + TPB - 1) / TPB;
    edges_kernel<<<nb_f, TPB>>>(pts, faces, F, M, off2, n1, n2);

    fused_mid<<<1, 1024>>>(off2, n2);

    int Mj = M - 5;
    int nb_w = (n1 + TPB - 1) / TPB;
    window_kernel<<<nb_w, TPB>>>(M, Mj, n1, off2);

    final1_kernel<<<148, TPB>>>(nb_f, nb_w);
    final2_kernel<<<1, 256>>>(148, (float*)d_out);
}